// round 9
// baseline (speedup 1.0000x reference)
#include <cuda_runtime.h>
#include <cstdint>

// ---------------------------------------------------------------------------
// Problem constants (fixed by the dataset)
// ---------------------------------------------------------------------------
#define N_MOL 200000
#define E_MOL 1000000
#define N_CLQ 120000
#define E_CLQ 500000
#define NG    4096

// ---------------------------------------------------------------------------
// Static device scratch (no allocations allowed anywhere)
// ---------------------------------------------------------------------------
__device__ float g_mh1[(size_t)N_MOL * 156];
__device__ float g_mh2[(size_t)N_MOL * 312];
__device__ float g_magg[(size_t)N_MOL * 156];
__device__ float g_mt [(size_t)N_MOL * 128];
__device__ float g_mh3[(size_t)N_MOL * 128];

__device__ float g_ch1[(size_t)N_CLQ * 184];
__device__ float g_ch2[(size_t)N_CLQ * 368];
__device__ float g_cagg[(size_t)N_CLQ * 184];
__device__ float g_ct [(size_t)N_CLQ * 128];
__device__ float g_ch3[(size_t)N_CLQ * 128];

// CSR structures (built once per launch, reused by all 3 layers per branch)
__device__ int g_indptr_m[N_MOL + 1];
__device__ int g_cursor_m[N_MOL + 1];
__device__ int g_indices_m[E_MOL];
__device__ int g_indptr_c[N_CLQ + 1];
__device__ int g_cursor_c[N_CLQ + 1];
__device__ int g_indices_c[E_CLQ];

// tf32-converted weights (12 matrices, 465040 elements total)
__device__ uint32_t g_wtf32[470000];

__device__ __forceinline__ uint32_t f32_to_tf32(float v) {
    uint32_t t;
    asm("cvt.rna.tf32.f32 %0, %1;" : "=r"(t) : "f"(v));
    return t;
}
__device__ __forceinline__ uint32_t bits_to_tf32(uint32_t b) {
    uint32_t t;
    asm("cvt.rna.tf32.f32 %0, %1;" : "=r"(t) : "f"(__uint_as_float(b)));
    return t;
}

// cp.async helpers (sm_80+; LDGSTS on sm_100a). src-size 0 => zero-fill.
__device__ __forceinline__ void cp16(uint32_t dst, const void* src, int bytes) {
    asm volatile("cp.async.cg.shared.global [%0], [%1], 16, %2;"
                 :: "r"(dst), "l"(src), "r"(bytes));
}
__device__ __forceinline__ void cp8(uint32_t dst, const void* src, int bytes) {
    asm volatile("cp.async.ca.shared.global [%0], [%1], 8, %2;"
                 :: "r"(dst), "l"(src), "r"(bytes));
}
#define CP_COMMIT() asm volatile("cp.async.commit_group;")
#define CP_WAIT1()  asm volatile("cp.async.wait_group 1;")

// ---------------------------------------------------------------------------
// Fused weight pre-conversion: all 12 matrices in one launch
// ---------------------------------------------------------------------------
struct CvtArgs {
    const float* src[12];
    int off[13];
};

__global__ void cvt_all_kernel(CvtArgs a, uint32_t* __restrict__ out, int total)
{
    int i = blockIdx.x * blockDim.x + threadIdx.x;
    if (i >= total) return;
    int m = 0;
#pragma unroll
    for (int j = 1; j < 12; j++) if (i >= a.off[j]) m = j;
    out[i] = f32_to_tf32(a.src[m][i - a.off[m]]);
}

// ---------------------------------------------------------------------------
// CSR build: histogram -> single-block scan -> cursor copy -> scatter
// ---------------------------------------------------------------------------
__global__ void hist_kernel(const int* __restrict__ dst, int E, int* __restrict__ deg)
{
    int e = blockIdx.x * blockDim.x + threadIdx.x;
    if (e < E) atomicAdd(&deg[dst[e]], 1);
}

__global__ void scan_kernel(const int* __restrict__ deg, int n, int* __restrict__ indptr)
{
    __shared__ int sh[1024];
    __shared__ int carry;
    int tid = threadIdx.x;
    if (tid == 0) { carry = 0; indptr[0] = 0; }
    __syncthreads();
    for (int base = 0; base < n; base += 1024) {
        int i = base + tid;
        int v = (i < n) ? deg[i] : 0;
        sh[tid] = v;
        __syncthreads();
#pragma unroll
        for (int off = 1; off < 1024; off <<= 1) {
            int t = (tid >= off) ? sh[tid - off] : 0;
            __syncthreads();
            sh[tid] += t;
            __syncthreads();
        }
        if (i < n) indptr[i + 1] = sh[tid] + carry;
        __syncthreads();
        if (tid == 0) carry += sh[1023];
        __syncthreads();
    }
}

__global__ void copy_kernel(const int* __restrict__ in, int* __restrict__ out, int n)
{
    int i = blockIdx.x * blockDim.x + threadIdx.x;
    if (i < n) out[i] = in[i];
}

__global__ void scatter_kernel(const int* __restrict__ src, const int* __restrict__ dst,
                               int E, int* __restrict__ cursor, int* __restrict__ indices)
{
    int e = blockIdx.x * blockDim.x + threadIdx.x;
    if (e >= E) return;
    int pos = atomicAdd(&cursor[dst[e]], 1);
    indices[pos] = src[e];
}

// ---------------------------------------------------------------------------
// CSR gather aggregation: one warp per destination node, x2 edge unroll,
// both chunk slots guarded (chunks may be <32, e.g. dim=92 VEC=4 -> 23).
// ---------------------------------------------------------------------------
template <int VEC>
__global__ void csr_agg(const float* __restrict__ feat,
                        const int* __restrict__ indptr,
                        const int* __restrict__ indices,
                        float* __restrict__ aggout, int N, int dim)
{
    int w = blockIdx.x * 8 + (threadIdx.x >> 5);
    if (w >= N) return;
    int lane = threadIdx.x & 31;
    int beg = __ldg(indptr + w);
    int end = __ldg(indptr + w + 1);
    int chunks = dim / VEC;
    bool has0 = lane < chunks;
    bool has1 = (lane + 32) < chunks;

    if (VEC == 4) {
        float4 a0 = make_float4(0.f, 0.f, 0.f, 0.f);
        float4 a1 = make_float4(0.f, 0.f, 0.f, 0.f);
        int i = beg;
        for (; i + 1 < end; i += 2) {
            int s0 = __ldg(indices + i);
            int s1 = __ldg(indices + i + 1);
            const float4* p0 = reinterpret_cast<const float4*>(feat + (size_t)s0 * dim);
            const float4* p1 = reinterpret_cast<const float4*>(feat + (size_t)s1 * dim);
            if (has0) {
                float4 v0 = __ldg(p0 + lane);
                float4 u0 = __ldg(p1 + lane);
                a0.x += v0.x + u0.x; a0.y += v0.y + u0.y;
                a0.z += v0.z + u0.z; a0.w += v0.w + u0.w;
            }
            if (has1) {
                float4 v1 = __ldg(p0 + lane + 32);
                float4 u1 = __ldg(p1 + lane + 32);
                a1.x += v1.x + u1.x; a1.y += v1.y + u1.y;
                a1.z += v1.z + u1.z; a1.w += v1.w + u1.w;
            }
        }
        if (i < end) {
            int s = __ldg(indices + i);
            const float4* p = reinterpret_cast<const float4*>(feat + (size_t)s * dim);
            if (has0) {
                float4 v0 = __ldg(p + lane);
                a0.x += v0.x; a0.y += v0.y; a0.z += v0.z; a0.w += v0.w;
            }
            if (has1) {
                float4 v1 = __ldg(p + lane + 32);
                a1.x += v1.x; a1.y += v1.y; a1.z += v1.z; a1.w += v1.w;
            }
        }
        float4* q = reinterpret_cast<float4*>(aggout + (size_t)w * dim);
        if (has0) q[lane] = a0;
        if (has1) q[lane + 32] = a1;
    } else {
        float2 a0 = make_float2(0.f, 0.f);
        float2 a1 = make_float2(0.f, 0.f);
        int i = beg;
        for (; i + 1 < end; i += 2) {
            int s0 = __ldg(indices + i);
            int s1 = __ldg(indices + i + 1);
            const float2* p0 = reinterpret_cast<const float2*>(feat + (size_t)s0 * dim);
            const float2* p1 = reinterpret_cast<const float2*>(feat + (size_t)s1 * dim);
            if (has0) {
                float2 v0 = __ldg(p0 + lane);
                float2 u0 = __ldg(p1 + lane);
                a0.x += v0.x + u0.x; a0.y += v0.y + u0.y;
            }
            if (has1) {
                float2 v1 = __ldg(p0 + lane + 32);
                float2 u1 = __ldg(p1 + lane + 32);
                a1.x += v1.x + u1.x; a1.y += v1.y + u1.y;
            }
        }
        if (i < end) {
            int s = __ldg(indices + i);
            const float2* p = reinterpret_cast<const float2*>(feat + (size_t)s * dim);
            if (has0) {
                float2 v0 = __ldg(p + lane);
                a0.x += v0.x; a0.y += v0.y;
            }
            if (has1) {
                float2 v1 = __ldg(p + lane + 32);
                a1.x += v1.x; a1.y += v1.y;
            }
        }
        float2* q = reinterpret_cast<float2*>(aggout + (size_t)w * dim);
        if (has0) q[lane] = a0;
        if (has1) q[lane + 32] = a1;
    }
}

// ---------------------------------------------------------------------------
// TF32 tensor-core fused SAGE GEMM, 3-stage cp.async pipeline.
//   out = act( A1 @ W1^T  [+ A2 @ W2^T]  [+ Cin]  [+ bias] )
// A*: [N,K] f32 row-major; staged raw via cp.async, converted to tf32 with
//     cvt.rna AT FRAGMENT LOAD (restores R4/R7 numerics, keeps pipeline).
// W*: [O,K] tf32(rna) bit patterns, pre-converted.
// Block tile 128x128, BK=16, 256 threads = 8 warps (2M x 4N),
// warp tile 64x32 via 4x4 m16n8k8 MMA, fp32 accumulation.
// ---------------------------------------------------------------------------
constexpr int GBK = 16, GSW = 20, GSTAGES = 3;
constexpr int G_AW  = 128 * GSW;        // words per A (or W) tile per stage
constexpr int G_STW = 2 * G_AW;         // words per stage
constexpr int GEMM_SMEM_BYTES = GSTAGES * G_STW * 4;   // 61440

template <int VEC, bool HAS2, bool HASC, bool BIAS, bool RELU>
__global__ __launch_bounds__(256)
void gemm_kernel(const float* __restrict__ A1, const uint32_t* __restrict__ W1,
                 const float* __restrict__ A2, const uint32_t* __restrict__ W2,
                 const float* __restrict__ Cin, const float* __restrict__ bias,
                 float* __restrict__ out, int N, int K, int O)
{
    extern __shared__ __align__(16) uint32_t dynsmem[];
    const uint32_t smem_u32 = (uint32_t)__cvta_generic_to_shared(dynsmem);

    const int tid  = threadIdx.x;
    const int lane = tid & 31;
    const int warp = tid >> 5;
    const int wm   = warp & 1;
    const int wn   = warp >> 1;
    const int grp  = lane >> 2;
    const int qid  = lane & 3;
    const int bm0  = blockIdx.y * 128;
    const int bn0  = blockIdx.x * 128;

    const int nk = (K + GBK - 1) / GBK;
    const int T  = (HAS2 ? 2 : 1) * nk;

    auto issue_tile = [&](int t) {
        const float*    A;
        const uint32_t* W;
        int k0;
        if (HAS2 && t >= nk) { A = A2; W = W2; k0 = (t - nk) * GBK; }
        else                 { A = A1; W = W1; k0 = t * GBK; }
        int st = t % GSTAGES;
        uint32_t aBase = smem_u32 + (uint32_t)(st * G_STW) * 4u;
        uint32_t wBase = aBase + (uint32_t)G_AW * 4u;
        if (VEC == 4) {
#pragma unroll
            for (int i = 0; i < 2; i++) {
                int c = tid + i * 256;              // 0..511
                int r = c >> 2, kc = (c & 3) * 4;
                int gr = min(bm0 + r, N - 1);
                int go = min(bn0 + r, O - 1);
                int bytes = (k0 + kc) < K ? 16 : 0;
                int ko = bytes ? (k0 + kc) : 0;
                uint32_t doff = (uint32_t)(r * GSW + kc) * 4u;
                cp16(aBase + doff, A + (size_t)gr * K + ko, bytes);
                cp16(wBase + doff, W + (size_t)go * K + ko, bytes);
            }
        } else {
#pragma unroll
            for (int i = 0; i < 4; i++) {
                int c = tid + i * 256;              // 0..1023
                int r = c >> 3, kc = (c & 7) * 2;
                int gr = min(bm0 + r, N - 1);
                int go = min(bn0 + r, O - 1);
                int bytes = (k0 + kc) < K ? 8 : 0;
                int ko = bytes ? (k0 + kc) : 0;
                uint32_t doff = (uint32_t)(r * GSW + kc) * 4u;
                cp8(aBase + doff, A + (size_t)gr * K + ko, bytes);
                cp8(wBase + doff, W + (size_t)go * K + ko, bytes);
            }
        }
    };

    float acc[4][4][4];
#pragma unroll
    for (int i = 0; i < 4; i++)
#pragma unroll
        for (int j = 0; j < 4; j++)
#pragma unroll
            for (int f = 0; f < 4; f++) acc[i][j][f] = 0.f;

    // prologue: fill STAGES-1 stages
#pragma unroll
    for (int s = 0; s < GSTAGES - 1; s++) {
        if (s < T) issue_tile(s);
        CP_COMMIT();
    }

    for (int t = 0; t < T; t++) {
        CP_WAIT1();
        __syncthreads();
        if (t + GSTAGES - 1 < T) issue_tile(t + GSTAGES - 1);
        CP_COMMIT();

        const uint32_t* Asb = dynsmem + (t % GSTAGES) * G_STW;
        const uint32_t* Wsb = Asb + G_AW;

#pragma unroll
        for (int ks = 0; ks < GBK; ks += 8) {
            uint32_t aF[4][4];
#pragma unroll
            for (int i = 0; i < 4; i++) {
                int r = wm * 64 + i * 16 + grp;
                // cvt.rna at fragment load: restores proper tf32 rounding of A
                aF[i][0] = bits_to_tf32(Asb[ r      * GSW + ks + qid]);
                aF[i][1] = bits_to_tf32(Asb[(r + 8) * GSW + ks + qid]);
                aF[i][2] = bits_to_tf32(Asb[ r      * GSW + ks + qid + 4]);
                aF[i][3] = bits_to_tf32(Asb[(r + 8) * GSW + ks + qid + 4]);
            }
            uint32_t bF[4][2];
#pragma unroll
            for (int j = 0; j < 4; j++) {
                int o = wn * 32 + j * 8 + grp;
                bF[j][0] = Wsb[o * GSW + ks + qid];
                bF[j][1] = Wsb[o * GSW + ks + qid + 4];
            }
#pragma unroll
            for (int i = 0; i < 4; i++)
#pragma unroll
                for (int j = 0; j < 4; j++) {
                    asm volatile(
                        "mma.sync.aligned.m16n8k8.row.col.f32.tf32.tf32.f32 "
                        "{%0,%1,%2,%3}, {%4,%5,%6,%7}, {%8,%9}, {%0,%1,%2,%3};"
                        : "+f"(acc[i][j][0]), "+f"(acc[i][j][1]),
                          "+f"(acc[i][j][2]), "+f"(acc[i][j][3])
                        : "r"(aF[i][0]), "r"(aF[i][1]),
                          "r"(aF[i][2]), "r"(aF[i][3]),
                          "r"(bF[j][0]), "r"(bF[j][1]));
                }
        }
        __syncthreads();
    }

    // epilogue (float2 stores; O always even, col0 even)
#pragma unroll
    for (int i = 0; i < 4; i++) {
        int row0 = bm0 + wm * 64 + i * 16 + grp;
#pragma unroll
        for (int j = 0; j < 4; j++) {
            int col0 = bn0 + wn * 32 + j * 8 + qid * 2;
            if (col0 >= O) continue;
            float2 bv;
            if (BIAS) bv = *reinterpret_cast<const float2*>(bias + col0);
#pragma unroll
            for (int h = 0; h < 2; h++) {
                int row = row0 + h * 8;
                if (row >= N) continue;
                float v0 = acc[i][j][h * 2 + 0];
                float v1 = acc[i][j][h * 2 + 1];
                if (BIAS) { v0 += bv.x; v1 += bv.y; }
                if (HASC) {
                    float2 cv = *reinterpret_cast<const float2*>(Cin + (size_t)row * O + col0);
                    v0 += cv.x; v1 += cv.y;
                }
                if (RELU) { v0 = fmaxf(v0, 0.f); v1 = fmaxf(v1, 0.f); }
                *reinterpret_cast<float2*>(out + (size_t)row * O + col0) = make_float2(v0, v1);
            }
        }
    }
}

// ---------------------------------------------------------------------------
// Global mean pool over sorted batch ids. One block per graph, 128 threads.
// ---------------------------------------------------------------------------
__global__ void pool_kernel(const float* __restrict__ h,
                            const int* __restrict__ batch,
                            int N, float* __restrict__ out, int col_off)
{
    int g = blockIdx.x;
    int lo = 0, hi = N;
    while (lo < hi) { int mid = (lo + hi) >> 1; if (batch[mid] < g) lo = mid + 1; else hi = mid; }
    int start = lo;
    hi = N;
    while (lo < hi) { int mid = (lo + hi) >> 1; if (batch[mid] < g + 1) lo = mid + 1; else hi = mid; }
    int end = lo;

    int c = threadIdx.x;
    float s = 0.f;
    for (int r = start; r < end; r++) s += h[(size_t)r * 128 + c];
    float cnt = (end > start) ? (float)(end - start) : 1.f;
    out[(size_t)g * 256 + col_off + c] = s / cnt;
}

// ---------------------------------------------------------------------------
// Host-side drivers
// ---------------------------------------------------------------------------
static inline dim3 gemm_grid(int N, int O) {
    return dim3((O + 127) / 128, (N + 127) / 128);
}

template <int VEC, bool HAS2, bool HASC, bool BIAS, bool RELU>
static void launch_gemm(const float* A1, const uint32_t* W1,
                        const float* A2, const uint32_t* W2,
                        const float* Cin, const float* bias,
                        float* out, int N, int K, int O)
{
    cudaFuncSetAttribute(gemm_kernel<VEC, HAS2, HASC, BIAS, RELU>,
                         cudaFuncAttributeMaxDynamicSharedMemorySize, GEMM_SMEM_BYTES);
    gemm_kernel<VEC, HAS2, HASC, BIAS, RELU>
        <<<gemm_grid(N, O), 256, GEMM_SMEM_BYTES>>>(A1, W1, A2, W2, Cin, bias, out, N, K, O);
}

static void build_csr(const int* src, const int* dst, int N, int E,
                      int* indptr, int* cursor, int* indices)
{
    cudaMemsetAsync(cursor, 0, (size_t)N * sizeof(int), 0);
    hist_kernel<<<(E + 255) / 256, 256>>>(dst, E, cursor);
    scan_kernel<<<1, 1024>>>(cursor, N, indptr);
    copy_kernel<<<(N + 255) / 256, 256>>>(indptr, cursor, N);
    scatter_kernel<<<(E + 255) / 256, 256>>>(src, dst, E, cursor, indices);
}

static void launch_agg(const float* feat, const int* indptr, const int* indices,
                       float* agg, int N, int dim)
{
    int blocks = (N + 7) / 8;
    if (dim % 4 == 0) csr_agg<4><<<blocks, 256>>>(feat, indptr, indices, agg, N, dim);
    else              csr_agg<2><<<blocks, 256>>>(feat, indptr, indices, agg, N, dim);
}

static void run_branch(const float* x, const int* indptr, const int* indices,
                       const int* batch, int N,
                       int d0, int d1, int d2,
                       const uint32_t* w1l, const float* b1, const uint32_t* w1r,
                       const uint32_t* w2l, const float* b2, const uint32_t* w2r,
                       const uint32_t* w3l, const float* b3, const uint32_t* w3r,
                       float* h1, float* h2, float* agg, float* t, float* h3,
                       float* out, int col_off, bool skip_l1_agg)
{
    // Layer 1
    if (!skip_l1_agg) launch_agg(x, indptr, indices, agg, N, d0);
    if (d0 % 4 == 0)
        launch_gemm<4, true, false, true, true>(agg, w1l, x, w1r, nullptr, b1, h1, N, d0, d1);
    else
        launch_gemm<2, true, false, true, true>(agg, w1l, x, w1r, nullptr, b1, h1, N, d0, d1);

    // Layer 2
    launch_agg(h1, indptr, indices, agg, N, d1);
    launch_gemm<4, true, false, true, true>(agg, w2l, h1, w2r, nullptr, b2, h2, N, d1, d2);

    // Layer 3 (transform-first)
    launch_gemm<4, false, false, false, false>(h2, w3l, nullptr, nullptr, nullptr, nullptr,
                                               t, N, d2, 128);
    launch_agg(t, indptr, indices, agg, N, 128);
    launch_gemm<4, false, true, true, true>(h2, w3r, nullptr, nullptr, agg, b3, h3, N, d2, 128);

    pool_kernel<<<NG, 128>>>(h3, batch, N, out, col_off);
}

extern "C" void kernel_launch(void* const* d_in, const int* in_sizes, int n_in,
                              void* d_out, int out_size)
{
    (void)n_in; (void)out_size; (void)in_sizes;

    const float* x        = (const float*)d_in[0];
    const int*   ei       = (const int*)  d_in[1];
    const int*   batch    = (const int*)  d_in[2];
    const float* xc       = (const float*)d_in[3];
    const int*   eic      = (const int*)  d_in[4];
    const int*   batchc   = (const int*)  d_in[5];

    const int wcnt[12] = {
        156*78, 156*78, 312*156, 312*156, 128*312, 128*312,
        184*92, 184*92, 368*184, 368*184, 128*368, 128*368
    };
    CvtArgs ca;
    ca.src[0]  = (const float*)d_in[6];   ca.src[1]  = (const float*)d_in[8];
    ca.src[2]  = (const float*)d_in[9];   ca.src[3]  = (const float*)d_in[11];
    ca.src[4]  = (const float*)d_in[12];  ca.src[5]  = (const float*)d_in[14];
    ca.src[6]  = (const float*)d_in[15];  ca.src[7]  = (const float*)d_in[17];
    ca.src[8]  = (const float*)d_in[18];  ca.src[9]  = (const float*)d_in[20];
    ca.src[10] = (const float*)d_in[21];  ca.src[11] = (const float*)d_in[23];
    ca.off[0] = 0;
    for (int i = 0; i < 12; i++) ca.off[i + 1] = ca.off[i] + wcnt[i];
    int wtotal = ca.off[12];

    const float* m1_bl = (const float*)d_in[7];
    const float* m2_bl = (const float*)d_in[10];
    const float* m3_bl = (const float*)d_in[13];
    const float* c1_bl = (const float*)d_in[16];
    const float* c2_bl = (const float*)d_in[19];
    const float* c3_bl = (const float*)d_in[22];

    float* out = (float*)d_out;

    float *mh1, *mh2, *magg, *mt, *mh3;
    float *ch1, *ch2, *cagg, *ct, *ch3;
    uint32_t* wt;
    int *ipm, *curm, *idxm, *ipc, *curc, *idxc;
    cudaGetSymbolAddress((void**)&mh1,  g_mh1);
    cudaGetSymbolAddress((void**)&mh2,  g_mh2);
    cudaGetSymbolAddress((void**)&magg, g_magg);
    cudaGetSymbolAddress((void**)&mt,   g_mt);
    cudaGetSymbolAddress((void**)&mh3,  g_mh3);
    cudaGetSymbolAddress((void**)&ch1,  g_ch1);
    cudaGetSymbolAddress((void**)&ch2,  g_ch2);
    cudaGetSymbolAddress((void**)&cagg, g_cagg);
    cudaGetSymbolAddress((void**)&ct,   g_ct);
    cudaGetSymbolAddress((void**)&ch3,  g_ch3);
    cudaGetSymbolAddress((void**)&wt,   g_wtf32);
    cudaGetSymbolAddress((void**)&ipm,  g_indptr_m);
    cudaGetSymbolAddress((void**)&curm, g_cursor_m);
    cudaGetSymbolAddress((void**)&idxm, g_indices_m);
    cudaGetSymbolAddress((void**)&ipc,  g_indptr_c);
    cudaGetSymbolAddress((void**)&curc, g_cursor_c);
    cudaGetSymbolAddress((void**)&idxc, g_indices_c);

    // Launch order puts mol L1 csr_agg at launch #6 so ncu (-s 5 -c 1)
    // profiles the aggregation kernel.
    build_csr(ei, ei + E_MOL, N_MOL, E_MOL, ipm, curm, idxm);        // launches 1-5
    launch_agg(x, ipm, idxm, magg, N_MOL, 78);                       // launch 6

    cvt_all_kernel<<<(wtotal + 255) / 256, 256>>>(ca, wt, wtotal);
    const uint32_t* wtf[12];
    for (int i = 0; i < 12; i++) wtf[i] = wt + ca.off[i];

    build_csr(eic, eic + E_CLQ, N_CLQ, E_CLQ, ipc, curc, idxc);

    // molecule branch: 78 -> 156 -> 312 -> 128, output cols [0,128)
    run_branch(x, ipm, idxm, batch, N_MOL,
               78, 156, 312,
               wtf[0], m1_bl, wtf[1], wtf[2], m2_bl, wtf[3], wtf[4], m3_bl, wtf[5],
               mh1, mh2, magg, mt, mh3, out, 0, /*skip_l1_agg=*/true);

    // clique branch: 92 -> 184 -> 368 -> 128, output cols [128,256)
    run_branch(xc, ipc, idxc, batchc, N_CLQ,
               92, 184, 368,
               wtf[6], c1_bl, wtf[7], wtf[8], c2_bl, wtf[9], wtf[10], c3_bl, wtf[11],
               ch1, ch2, cagg, ct, ch3, out, 128, /*skip_l1_agg=*/false);
}

// round 10
// speedup vs baseline: 1.1746x; 1.1746x over previous
#include <cuda_runtime.h>
#include <cstdint>

// ---------------------------------------------------------------------------
// Problem constants (fixed by the dataset)
// ---------------------------------------------------------------------------
#define N_MOL 200000
#define E_MOL 1000000
#define N_CLQ 120000
#define E_CLQ 500000
#define NG    4096

// ---------------------------------------------------------------------------
// Static device scratch (no allocations allowed anywhere)
// ---------------------------------------------------------------------------
__device__ float g_mh1[(size_t)N_MOL * 156];
__device__ float g_mh2[(size_t)N_MOL * 312];
__device__ float g_magg[(size_t)N_MOL * 156];
__device__ float g_mt [(size_t)N_MOL * 128];
__device__ float g_mh3[(size_t)N_MOL * 128];

__device__ float g_ch1[(size_t)N_CLQ * 184];
__device__ float g_ch2[(size_t)N_CLQ * 368];
__device__ float g_cagg[(size_t)N_CLQ * 184];
__device__ float g_ct [(size_t)N_CLQ * 128];
__device__ float g_ch3[(size_t)N_CLQ * 128];

// CSR structures (built once per launch, reused by all 3 layers per branch)
__device__ int g_indptr_m[N_MOL + 1];
__device__ int g_cursor_m[N_MOL + 1];
__device__ int g_indices_m[E_MOL];
__device__ int g_indptr_c[N_CLQ + 1];
__device__ int g_cursor_c[N_CLQ + 1];
__device__ int g_indices_c[E_CLQ];

// tf32-converted weights (12 matrices, 465040 elements total)
__device__ uint32_t g_wtf32[470000];

__device__ __forceinline__ uint32_t f32_to_tf32(float v) {
    uint32_t t;
    asm("cvt.rna.tf32.f32 %0, %1;" : "=r"(t) : "f"(v));
    return t;
}

__device__ __forceinline__ void ldsm_x4(uint32_t& r0, uint32_t& r1,
                                        uint32_t& r2, uint32_t& r3, uint32_t addr) {
    asm volatile("ldmatrix.sync.aligned.m8n8.x4.shared.b16 {%0,%1,%2,%3}, [%4];"
                 : "=r"(r0), "=r"(r1), "=r"(r2), "=r"(r3) : "r"(addr));
}

// ---------------------------------------------------------------------------
// Fused weight pre-conversion: all 12 matrices in one launch
// ---------------------------------------------------------------------------
struct CvtArgs {
    const float* src[12];
    int off[13];
};

__global__ void cvt_all_kernel(CvtArgs a, uint32_t* __restrict__ out, int total)
{
    int i = blockIdx.x * blockDim.x + threadIdx.x;
    if (i >= total) return;
    int m = 0;
#pragma unroll
    for (int j = 1; j < 12; j++) if (i >= a.off[j]) m = j;
    out[i] = f32_to_tf32(a.src[m][i - a.off[m]]);
}

// ---------------------------------------------------------------------------
// CSR build: histogram -> single-block scan -> cursor copy -> scatter
// ---------------------------------------------------------------------------
__global__ void hist_kernel(const int* __restrict__ dst, int E, int* __restrict__ deg)
{
    int e = blockIdx.x * blockDim.x + threadIdx.x;
    if (e < E) atomicAdd(&deg[dst[e]], 1);
}

__global__ void scan_kernel(const int* __restrict__ deg, int n, int* __restrict__ indptr)
{
    __shared__ int sh[1024];
    __shared__ int carry;
    int tid = threadIdx.x;
    if (tid == 0) { carry = 0; indptr[0] = 0; }
    __syncthreads();
    for (int base = 0; base < n; base += 1024) {
        int i = base + tid;
        int v = (i < n) ? deg[i] : 0;
        sh[tid] = v;
        __syncthreads();
#pragma unroll
        for (int off = 1; off < 1024; off <<= 1) {
            int t = (tid >= off) ? sh[tid - off] : 0;
            __syncthreads();
            sh[tid] += t;
            __syncthreads();
        }
        if (i < n) indptr[i + 1] = sh[tid] + carry;
        __syncthreads();
        if (tid == 0) carry += sh[1023];
        __syncthreads();
    }
}

__global__ void copy_kernel(const int* __restrict__ in, int* __restrict__ out, int n)
{
    int i = blockIdx.x * blockDim.x + threadIdx.x;
    if (i < n) out[i] = in[i];
}

__global__ void scatter_kernel(const int* __restrict__ src, const int* __restrict__ dst,
                               int E, int* __restrict__ cursor, int* __restrict__ indices)
{
    int e = blockIdx.x * blockDim.x + threadIdx.x;
    if (e >= E) return;
    int pos = atomicAdd(&cursor[dst[e]], 1);
    indices[pos] = src[e];
}

// ---------------------------------------------------------------------------
// CSR gather aggregation: one warp per destination node, x2 edge unroll,
// both chunk slots guarded (chunks may be <32, e.g. dim=92 VEC=4 -> 23).
// ---------------------------------------------------------------------------
template <int VEC>
__global__ void csr_agg(const float* __restrict__ feat,
                        const int* __restrict__ indptr,
                        const int* __restrict__ indices,
                        float* __restrict__ aggout, int N, int dim)
{
    int w = blockIdx.x * 8 + (threadIdx.x >> 5);
    if (w >= N) return;
    int lane = threadIdx.x & 31;
    int beg = __ldg(indptr + w);
    int end = __ldg(indptr + w + 1);
    int chunks = dim / VEC;
    bool has0 = lane < chunks;
    bool has1 = (lane + 32) < chunks;

    if (VEC == 4) {
        float4 a0 = make_float4(0.f, 0.f, 0.f, 0.f);
        float4 a1 = make_float4(0.f, 0.f, 0.f, 0.f);
        int i = beg;
        for (; i + 1 < end; i += 2) {
            int s0 = __ldg(indices + i);
            int s1 = __ldg(indices + i + 1);
            const float4* p0 = reinterpret_cast<const float4*>(feat + (size_t)s0 * dim);
            const float4* p1 = reinterpret_cast<const float4*>(feat + (size_t)s1 * dim);
            if (has0) {
                float4 v0 = __ldg(p0 + lane);
                float4 u0 = __ldg(p1 + lane);
                a0.x += v0.x + u0.x; a0.y += v0.y + u0.y;
                a0.z += v0.z + u0.z; a0.w += v0.w + u0.w;
            }
            if (has1) {
                float4 v1 = __ldg(p0 + lane + 32);
                float4 u1 = __ldg(p1 + lane + 32);
                a1.x += v1.x + u1.x; a1.y += v1.y + u1.y;
                a1.z += v1.z + u1.z; a1.w += v1.w + u1.w;
            }
        }
        if (i < end) {
            int s = __ldg(indices + i);
            const float4* p = reinterpret_cast<const float4*>(feat + (size_t)s * dim);
            if (has0) {
                float4 v0 = __ldg(p + lane);
                a0.x += v0.x; a0.y += v0.y; a0.z += v0.z; a0.w += v0.w;
            }
            if (has1) {
                float4 v1 = __ldg(p + lane + 32);
                a1.x += v1.x; a1.y += v1.y; a1.z += v1.z; a1.w += v1.w;
            }
        }
        float4* q = reinterpret_cast<float4*>(aggout + (size_t)w * dim);
        if (has0) q[lane] = a0;
        if (has1) q[lane + 32] = a1;
    } else {
        float2 a0 = make_float2(0.f, 0.f);
        float2 a1 = make_float2(0.f, 0.f);
        int i = beg;
        for (; i + 1 < end; i += 2) {
            int s0 = __ldg(indices + i);
            int s1 = __ldg(indices + i + 1);
            const float2* p0 = reinterpret_cast<const float2*>(feat + (size_t)s0 * dim);
            const float2* p1 = reinterpret_cast<const float2*>(feat + (size_t)s1 * dim);
            if (has0) {
                float2 v0 = __ldg(p0 + lane);
                float2 u0 = __ldg(p1 + lane);
                a0.x += v0.x + u0.x; a0.y += v0.y + u0.y;
            }
            if (has1) {
                float2 v1 = __ldg(p0 + lane + 32);
                float2 u1 = __ldg(p1 + lane + 32);
                a1.x += v1.x + u1.x; a1.y += v1.y + u1.y;
            }
        }
        if (i < end) {
            int s = __ldg(indices + i);
            const float2* p = reinterpret_cast<const float2*>(feat + (size_t)s * dim);
            if (has0) {
                float2 v0 = __ldg(p + lane);
                a0.x += v0.x; a0.y += v0.y;
            }
            if (has1) {
                float2 v1 = __ldg(p + lane + 32);
                a1.x += v1.x; a1.y += v1.y;
            }
        }
        float2* q = reinterpret_cast<float2*>(aggout + (size_t)w * dim);
        if (has0) q[lane] = a0;
        if (has1) q[lane + 32] = a1;
    }
}

// ---------------------------------------------------------------------------
// TF32 tensor-core fused SAGE GEMM, reg-staged (R7) + LDMATRIX fragments.
//   out = act( A1 @ W1^T  [+ A2 @ W2^T]  [+ Cin]  [+ bias] )
// A*: [N,K] f32 row-major (cvt.rna at commit); W*: [O,K] tf32 pre-converted.
// 128x128 tile, BK=16, 256 threads = 8 warps (2M x 4N), warp 64x32.
// Fragment loads: ldmatrix.x4 (1 per A-frag, 1 per B-frag-pair) — the tf32
// m16n8k8 fragment map is exactly four 8x8-b32 quadrants.
// ---------------------------------------------------------------------------
template <int VEC, bool HAS2, bool HASC, bool BIAS, bool RELU>
__global__ __launch_bounds__(256, 2)
void gemm_kernel(const float* __restrict__ A1, const uint32_t* __restrict__ W1,
                 const float* __restrict__ A2, const uint32_t* __restrict__ W2,
                 const float* __restrict__ Cin, const float* __restrict__ bias,
                 float* __restrict__ out, int N, int K, int O)
{
    constexpr int BM = 128, BN = 128, BK = 16, SW = 20;
    __shared__ uint32_t As[BM][SW];
    __shared__ uint32_t Ws[BN][SW];

    const int tid  = threadIdx.x;
    const int lane = tid & 31;
    const int warp = tid >> 5;
    const int wm   = warp & 1;
    const int wn   = warp >> 1;
    const int grp  = lane >> 2;
    const int qid  = lane & 3;
    const int bm0  = blockIdx.y * BM;
    const int bn0  = blockIdx.x * BN;

    const int nk = (K + BK - 1) / BK;
    const int T  = (HAS2 ? 2 : 1) * nk;

    // ldmatrix per-lane base addresses (bytes, shared space)
    const uint32_t asBase = (uint32_t)__cvta_generic_to_shared(&As[0][0]);
    const uint32_t wsBase = (uint32_t)__cvta_generic_to_shared(&Ws[0][0]);
    // A-frag i: row = wm*64 + i*16 + (lane&7) + ((lane>>3)&1)*8, col = ((lane>>4)&1)*4
    uint32_t aAddr[4];
#pragma unroll
    for (int i = 0; i < 4; i++) {
        int r = wm * 64 + i * 16 + (lane & 7) + ((lane >> 3) & 1) * 8;
        int c = ((lane >> 4) & 1) * 4;
        aAddr[i] = asBase + (uint32_t)(r * SW + c) * 4u;
    }
    // B-frag pair jp (covers j=2*jp, 2*jp+1):
    // row = wn*32 + jp*16 + (lane&7) + ((lane>>4)&1)*8, col = ((lane>>3)&1)*4
    uint32_t bAddr[2];
#pragma unroll
    for (int jp = 0; jp < 2; jp++) {
        int r = wn * 32 + jp * 16 + (lane & 7) + ((lane >> 4) & 1) * 8;
        int c = ((lane >> 3) & 1) * 4;
        bAddr[jp] = wsBase + (uint32_t)(r * SW + c) * 4u;
    }

    float    regA[8];
    uint32_t regW[8];

    auto prefetch = [&](int t) {
        const float*    A;
        const uint32_t* W;
        int k0;
        if (HAS2 && t >= nk) { A = A2; W = W2; k0 = (t - nk) * BK; }
        else                 { A = A1; W = W1; k0 = t * BK; }
        if (VEC == 4) {
#pragma unroll
            for (int i = 0; i < 2; i++) {
                int r = (tid >> 2) + i * 64;
                int k = (tid & 3) * 4;
                bool ok = (k0 + k) < K;
                int gr = min(bm0 + r, N - 1);
                int go = min(bn0 + r, O - 1);
                float4 va = ok ? *reinterpret_cast<const float4*>(A + (size_t)gr * K + k0 + k)
                               : make_float4(0.f, 0.f, 0.f, 0.f);
                uint4  vw = ok ? *reinterpret_cast<const uint4*>(W + (size_t)go * K + k0 + k)
                               : make_uint4(0u, 0u, 0u, 0u);
                regA[i*4+0] = va.x; regA[i*4+1] = va.y; regA[i*4+2] = va.z; regA[i*4+3] = va.w;
                regW[i*4+0] = vw.x; regW[i*4+1] = vw.y; regW[i*4+2] = vw.z; regW[i*4+3] = vw.w;
            }
        } else {
#pragma unroll
            for (int i = 0; i < 4; i++) {
                int r = (tid >> 3) + i * 32;
                int k = (tid & 7) * 2;
                bool ok = (k0 + k) < K;
                int gr = min(bm0 + r, N - 1);
                int go = min(bn0 + r, O - 1);
                float2 va = ok ? *reinterpret_cast<const float2*>(A + (size_t)gr * K + k0 + k)
                               : make_float2(0.f, 0.f);
                uint2  vw = ok ? *reinterpret_cast<const uint2*>(W + (size_t)go * K + k0 + k)
                               : make_uint2(0u, 0u);
                regA[i*2+0] = va.x; regA[i*2+1] = va.y;
                regW[i*2+0] = vw.x; regW[i*2+1] = vw.y;
            }
        }
    };

    auto commit = [&]() {
        if (VEC == 4) {
#pragma unroll
            for (int i = 0; i < 2; i++) {
                int r = (tid >> 2) + i * 64;
                int k = (tid & 3) * 4;
                uint4 ua = make_uint4(f32_to_tf32(regA[i*4+0]), f32_to_tf32(regA[i*4+1]),
                                      f32_to_tf32(regA[i*4+2]), f32_to_tf32(regA[i*4+3]));
                *reinterpret_cast<uint4*>(&As[r][k]) = ua;
                *reinterpret_cast<uint4*>(&Ws[r][k]) =
                    make_uint4(regW[i*4+0], regW[i*4+1], regW[i*4+2], regW[i*4+3]);
            }
        } else {
#pragma unroll
            for (int i = 0; i < 4; i++) {
                int r = (tid >> 3) + i * 32;
                int k = (tid & 7) * 2;
                *reinterpret_cast<uint2*>(&As[r][k]) =
                    make_uint2(f32_to_tf32(regA[i*2+0]), f32_to_tf32(regA[i*2+1]));
                *reinterpret_cast<uint2*>(&Ws[r][k]) = make_uint2(regW[i*2+0], regW[i*2+1]);
            }
        }
    };

    float acc[4][4][4];
#pragma unroll
    for (int i = 0; i < 4; i++)
#pragma unroll
        for (int j = 0; j < 4; j++)
#pragma unroll
            for (int f = 0; f < 4; f++) acc[i][j][f] = 0.f;

    prefetch(0);
    for (int t = 0; t < T; t++) {
        __syncthreads();
        commit();
        __syncthreads();
        if (t + 1 < T) prefetch(t + 1);   // overlaps the MMA work below

#pragma unroll
        for (int ks = 0; ks < BK; ks += 8) {
            uint32_t aF[4][4];
#pragma unroll
            for (int i = 0; i < 4; i++)
                ldsm_x4(aF[i][0], aF[i][1], aF[i][2], aF[i][3], aAddr[i] + (uint32_t)ks * 4u);
            uint32_t bF[4][2];
#pragma unroll
            for (int jp = 0; jp < 2; jp++)
                ldsm_x4(bF[jp*2][0], bF[jp*2][1], bF[jp*2+1][0], bF[jp*2+1][1],
                        bAddr[jp] + (uint32_t)ks * 4u);
#pragma unroll
            for (int i = 0; i < 4; i++)
#pragma unroll
                for (int j = 0; j < 4; j++) {
                    asm volatile(
                        "mma.sync.aligned.m16n8k8.row.col.f32.tf32.tf32.f32 "
                        "{%0,%1,%2,%3}, {%4,%5,%6,%7}, {%8,%9}, {%0,%1,%2,%3};"
                        : "+f"(acc[i][j][0]), "+f"(acc[i][j][1]),
                          "+f"(acc[i][j][2]), "+f"(acc[i][j][3])
                        : "r"(aF[i][0]), "r"(aF[i][1]),
                          "r"(aF[i][2]), "r"(aF[i][3]),
                          "r"(bF[j][0]), "r"(bF[j][1]));
                }
        }
    }

    // epilogue (float2 stores; O always even, col0 even)
#pragma unroll
    for (int i = 0; i < 4; i++) {
        int row0 = bm0 + wm * 64 + i * 16 + grp;
#pragma unroll
        for (int j = 0; j < 4; j++) {
            int col0 = bn0 + wn * 32 + j * 8 + qid * 2;
            if (col0 >= O) continue;
            float2 bv;
            if (BIAS) bv = *reinterpret_cast<const float2*>(bias + col0);
#pragma unroll
            for (int h = 0; h < 2; h++) {
                int row = row0 + h * 8;
                if (row >= N) continue;
                float v0 = acc[i][j][h * 2 + 0];
                float v1 = acc[i][j][h * 2 + 1];
                if (BIAS) { v0 += bv.x; v1 += bv.y; }
                if (HASC) {
                    float2 cv = *reinterpret_cast<const float2*>(Cin + (size_t)row * O + col0);
                    v0 += cv.x; v1 += cv.y;
                }
                if (RELU) { v0 = fmaxf(v0, 0.f); v1 = fmaxf(v1, 0.f); }
                *reinterpret_cast<float2*>(out + (size_t)row * O + col0) = make_float2(v0, v1);
            }
        }
    }
}

// ---------------------------------------------------------------------------
// Global mean pool over sorted batch ids. One block per graph, 128 threads.
// ---------------------------------------------------------------------------
__global__ void pool_kernel(const float* __restrict__ h,
                            const int* __restrict__ batch,
                            int N, float* __restrict__ out, int col_off)
{
    int g = blockIdx.x;
    int lo = 0, hi = N;
    while (lo < hi) { int mid = (lo + hi) >> 1; if (batch[mid] < g) lo = mid + 1; else hi = mid; }
    int start = lo;
    hi = N;
    while (lo < hi) { int mid = (lo + hi) >> 1; if (batch[mid] < g + 1) lo = mid + 1; else hi = mid; }
    int end = lo;

    int c = threadIdx.x;
    float s = 0.f;
    for (int r = start; r < end; r++) s += h[(size_t)r * 128 + c];
    float cnt = (end > start) ? (float)(end - start) : 1.f;
    out[(size_t)g * 256 + col_off + c] = s / cnt;
}

// ---------------------------------------------------------------------------
// Host-side drivers
// ---------------------------------------------------------------------------
static inline dim3 gemm_grid(int N, int O) {
    return dim3((O + 127) / 128, (N + 127) / 128);
}

static void build_csr(const int* src, const int* dst, int N, int E,
                      int* indptr, int* cursor, int* indices)
{
    cudaMemsetAsync(cursor, 0, (size_t)N * sizeof(int), 0);
    hist_kernel<<<(E + 255) / 256, 256>>>(dst, E, cursor);
    scan_kernel<<<1, 1024>>>(cursor, N, indptr);
    copy_kernel<<<(N + 255) / 256, 256>>>(indptr, cursor, N);
    scatter_kernel<<<(E + 255) / 256, 256>>>(src, dst, E, cursor, indices);
}

static void launch_agg(const float* feat, const int* indptr, const int* indices,
                       float* agg, int N, int dim)
{
    int blocks = (N + 7) / 8;
    if (dim % 4 == 0) csr_agg<4><<<blocks, 256>>>(feat, indptr, indices, agg, N, dim);
    else              csr_agg<2><<<blocks, 256>>>(feat, indptr, indices, agg, N, dim);
}

static void run_branch(const float* x, const int* indptr, const int* indices,
                       const int* batch, int N,
                       int d0, int d1, int d2,
                       const uint32_t* w1l, const float* b1, const uint32_t* w1r,
                       const uint32_t* w2l, const float* b2, const uint32_t* w2r,
                       const uint32_t* w3l, const float* b3, const uint32_t* w3r,
                       float* h1, float* h2, float* agg, float* t, float* h3,
                       float* out, int col_off, bool skip_l1_agg)
{
    // Layer 1
    if (!skip_l1_agg) launch_agg(x, indptr, indices, agg, N, d0);
    if (d0 % 4 == 0)
        gemm_kernel<4, true, false, true, true><<<gemm_grid(N, d1), 256>>>(
            agg, w1l, x, w1r, nullptr, b1, h1, N, d0, d1);
    else
        gemm_kernel<2, true, false, true, true><<<gemm_grid(N, d1), 256>>>(
            agg, w1l, x, w1r, nullptr, b1, h1, N, d0, d1);

    // Layer 2
    launch_agg(h1, indptr, indices, agg, N, d1);
    gemm_kernel<4, true, false, true, true><<<gemm_grid(N, d2), 256>>>(
        agg, w2l, h1, w2r, nullptr, b2, h2, N, d1, d2);

    // Layer 3 (transform-first)
    gemm_kernel<4, false, false, false, false><<<gemm_grid(N, 128), 256>>>(
        h2, w3l, nullptr, nullptr, nullptr, nullptr, t, N, d2, 128);
    launch_agg(t, indptr, indices, agg, N, 128);
    gemm_kernel<4, false, true, true, true><<<gemm_grid(N, 128), 256>>>(
        h2, w3r, nullptr, nullptr, agg, b3, h3, N, d2, 128);

    pool_kernel<<<NG, 128>>>(h3, batch, N, out, col_off);
}

extern "C" void kernel_launch(void* const* d_in, const int* in_sizes, int n_in,
                              void* d_out, int out_size)
{
    (void)n_in; (void)out_size; (void)in_sizes;

    const float* x        = (const float*)d_in[0];
    const int*   ei       = (const int*)  d_in[1];
    const int*   batch    = (const int*)  d_in[2];
    const float* xc       = (const float*)d_in[3];
    const int*   eic      = (const int*)  d_in[4];
    const int*   batchc   = (const int*)  d_in[5];

    const int wcnt[12] = {
        156*78, 156*78, 312*156, 312*156, 128*312, 128*312,
        184*92, 184*92, 368*184, 368*184, 128*368, 128*368
    };
    CvtArgs ca;
    ca.src[0]  = (const float*)d_in[6];   ca.src[1]  = (const float*)d_in[8];
    ca.src[2]  = (const float*)d_in[9];   ca.src[3]  = (const float*)d_in[11];
    ca.src[4]  = (const float*)d_in[12];  ca.src[5]  = (const float*)d_in[14];
    ca.src[6]  = (const float*)d_in[15];  ca.src[7]  = (const float*)d_in[17];
    ca.src[8]  = (const float*)d_in[18];  ca.src[9]  = (const float*)d_in[20];
    ca.src[10] = (const float*)d_in[21];  ca.src[11] = (const float*)d_in[23];
    ca.off[0] = 0;
    for (int i = 0; i < 12; i++) ca.off[i + 1] = ca.off[i] + wcnt[i];
    int wtotal = ca.off[12];

    const float* m1_bl = (const float*)d_in[7];
    const float* m2_bl = (const float*)d_in[10];
    const float* m3_bl = (const float*)d_in[13];
    const float* c1_bl = (const float*)d_in[16];
    const float* c2_bl = (const float*)d_in[19];
    const float* c3_bl = (const float*)d_in[22];

    float* out = (float*)d_out;

    float *mh1, *mh2, *magg, *mt, *mh3;
    float *ch1, *ch2, *cagg, *ct, *ch3;
    uint32_t* wt;
    int *ipm, *curm, *idxm, *ipc, *curc, *idxc;
    cudaGetSymbolAddress((void**)&mh1,  g_mh1);
    cudaGetSymbolAddress((void**)&mh2,  g_mh2);
    cudaGetSymbolAddress((void**)&magg, g_magg);
    cudaGetSymbolAddress((void**)&mt,   g_mt);
    cudaGetSymbolAddress((void**)&mh3,  g_mh3);
    cudaGetSymbolAddress((void**)&ch1,  g_ch1);
    cudaGetSymbolAddress((void**)&ch2,  g_ch2);
    cudaGetSymbolAddress((void**)&cagg, g_cagg);
    cudaGetSymbolAddress((void**)&ct,   g_ct);
    cudaGetSymbolAddress((void**)&ch3,  g_ch3);
    cudaGetSymbolAddress((void**)&wt,   g_wtf32);
    cudaGetSymbolAddress((void**)&ipm,  g_indptr_m);
    cudaGetSymbolAddress((void**)&curm, g_cursor_m);
    cudaGetSymbolAddress((void**)&idxm, g_indices_m);
    cudaGetSymbolAddress((void**)&ipc,  g_indptr_c);
    cudaGetSymbolAddress((void**)&curc, g_cursor_c);
    cudaGetSymbolAddress((void**)&idxc, g_indices_c);

    // Launch order puts mol L1 csr_agg around the ncu -s 5 window.
    build_csr(ei, ei + E_MOL, N_MOL, E_MOL, ipm, curm, idxm);
    launch_agg(x, ipm, idxm, magg, N_MOL, 78);

    cvt_all_kernel<<<(wtotal + 255) / 256, 256>>>(ca, wt, wtotal);
    const uint32_t* wtf[12];
    for (int i = 0; i < 12; i++) wtf[i] = wt + ca.off[i];

    build_csr(eic, eic + E_CLQ, N_CLQ, E_CLQ, ipc, curc, idxc);

    // molecule branch: 78 -> 156 -> 312 -> 128, output cols [0,128)
    run_branch(x, ipm, idxm, batch, N_MOL,
               78, 156, 312,
               wtf[0], m1_bl, wtf[1], wtf[2], m2_bl, wtf[3], wtf[4], m3_bl, wtf[5],
               mh1, mh2, magg, mt, mh3, out, 0, /*skip_l1_agg=*/true);

    // clique branch: 92 -> 184 -> 368 -> 128, output cols [128,256)
    run_branch(xc, ipc, idxc, batchc, N_CLQ,
               92, 184, 368,
               wtf[6], c1_bl, wtf[7], wtf[8], c2_bl, wtf[9], wtf[10], c3_bl, wtf[11],
               ch1, ch2, cagg, ct, ch3, out, 128, /*skip_l1_agg=*/false);
}

// round 11
// speedup vs baseline: 1.3967x; 1.1891x over previous
#include <cuda_runtime.h>
#include <cstdint>

// ---------------------------------------------------------------------------
// Problem constants (fixed by the dataset)
// ---------------------------------------------------------------------------
#define N_MOL 200000
#define E_MOL 1000000
#define N_CLQ 120000
#define E_CLQ 500000
#define NG    4096

// ---------------------------------------------------------------------------
// Static device scratch (no allocations allowed anywhere)
// ---------------------------------------------------------------------------
__device__ float g_mh1[(size_t)N_MOL * 156];
__device__ float g_mh2[(size_t)N_MOL * 312];
__device__ float g_magg[(size_t)N_MOL * 156];
__device__ float g_mt [(size_t)N_MOL * 128];
__device__ float g_mh3[(size_t)N_MOL * 128];

__device__ float g_ch1[(size_t)N_CLQ * 184];
__device__ float g_ch2[(size_t)N_CLQ * 368];
__device__ float g_cagg[(size_t)N_CLQ * 184];
__device__ float g_ct [(size_t)N_CLQ * 128];
__device__ float g_ch3[(size_t)N_CLQ * 128];

// CSR structures (built once per launch, reused by all 3 layers per branch)
__device__ int g_indptr_m[N_MOL + 1];
__device__ int g_cursor_m[N_MOL + 1];
__device__ int g_indices_m[E_MOL];
__device__ int g_indptr_c[N_CLQ + 1];
__device__ int g_cursor_c[N_CLQ + 1];
__device__ int g_indices_c[E_CLQ];

// tf32-converted weights (12 matrices, 465040 elements total)
__device__ uint32_t g_wtf32[470000];

__device__ __forceinline__ uint32_t f32_to_tf32(float v) {
    uint32_t t;
    asm("cvt.rna.tf32.f32 %0, %1;" : "=r"(t) : "f"(v));
    return t;
}

__device__ __forceinline__ void ldsm_x4(uint32_t& r0, uint32_t& r1,
                                        uint32_t& r2, uint32_t& r3, uint32_t addr) {
    asm volatile("ldmatrix.sync.aligned.m8n8.x4.shared.b16 {%0,%1,%2,%3}, [%4];"
                 : "=r"(r0), "=r"(r1), "=r"(r2), "=r"(r3) : "r"(addr));
}

// ---------------------------------------------------------------------------
// Fused weight pre-conversion: all 12 matrices in one launch
// ---------------------------------------------------------------------------
struct CvtArgs {
    const float* src[12];
    int off[13];
};

__global__ void cvt_all_kernel(CvtArgs a, uint32_t* __restrict__ out, int total)
{
    int i = blockIdx.x * blockDim.x + threadIdx.x;
    if (i >= total) return;
    int m = 0;
#pragma unroll
    for (int j = 1; j < 12; j++) if (i >= a.off[j]) m = j;
    out[i] = f32_to_tf32(a.src[m][i - a.off[m]]);
}

// ---------------------------------------------------------------------------
// CSR build: histogram -> single-block scan -> cursor copy -> scatter
// ---------------------------------------------------------------------------
__global__ void hist_kernel(const int* __restrict__ dst, int E, int* __restrict__ deg)
{
    int e = blockIdx.x * blockDim.x + threadIdx.x;
    if (e < E) atomicAdd(&deg[dst[e]], 1);
}

__global__ void scan_kernel(const int* __restrict__ deg, int n, int* __restrict__ indptr)
{
    __shared__ int sh[1024];
    __shared__ int carry;
    int tid = threadIdx.x;
    if (tid == 0) { carry = 0; indptr[0] = 0; }
    __syncthreads();
    for (int base = 0; base < n; base += 1024) {
        int i = base + tid;
        int v = (i < n) ? deg[i] : 0;
        sh[tid] = v;
        __syncthreads();
#pragma unroll
        for (int off = 1; off < 1024; off <<= 1) {
            int t = (tid >= off) ? sh[tid - off] : 0;
            __syncthreads();
            sh[tid] += t;
            __syncthreads();
        }
        if (i < n) indptr[i + 1] = sh[tid] + carry;
        __syncthreads();
        if (tid == 0) carry += sh[1023];
        __syncthreads();
    }
}

__global__ void copy_kernel(const int* __restrict__ in, int* __restrict__ out, int n)
{
    int i = blockIdx.x * blockDim.x + threadIdx.x;
    if (i < n) out[i] = in[i];
}

__global__ void scatter_kernel(const int* __restrict__ src, const int* __restrict__ dst,
                               int E, int* __restrict__ cursor, int* __restrict__ indices)
{
    int e = blockIdx.x * blockDim.x + threadIdx.x;
    if (e >= E) return;
    int pos = atomicAdd(&cursor[dst[e]], 1);
    indices[pos] = src[e];
}

// ---------------------------------------------------------------------------
// CSR gather aggregation: one warp per destination node, x2 edge unroll,
// both chunk slots guarded (chunks may be <32, e.g. dim=92 VEC=4 -> 23).
// ---------------------------------------------------------------------------
template <int VEC>
__global__ void csr_agg(const float* __restrict__ feat,
                        const int* __restrict__ indptr,
                        const int* __restrict__ indices,
                        float* __restrict__ aggout, int N, int dim)
{
    int w = blockIdx.x * 8 + (threadIdx.x >> 5);
    if (w >= N) return;
    int lane = threadIdx.x & 31;
    int beg = __ldg(indptr + w);
    int end = __ldg(indptr + w + 1);
    int chunks = dim / VEC;
    bool has0 = lane < chunks;
    bool has1 = (lane + 32) < chunks;

    if (VEC == 4) {
        float4 a0 = make_float4(0.f, 0.f, 0.f, 0.f);
        float4 a1 = make_float4(0.f, 0.f, 0.f, 0.f);
        int i = beg;
        for (; i + 1 < end; i += 2) {
            int s0 = __ldg(indices + i);
            int s1 = __ldg(indices + i + 1);
            const float4* p0 = reinterpret_cast<const float4*>(feat + (size_t)s0 * dim);
            const float4* p1 = reinterpret_cast<const float4*>(feat + (size_t)s1 * dim);
            if (has0) {
                float4 v0 = __ldg(p0 + lane);
                float4 u0 = __ldg(p1 + lane);
                a0.x += v0.x + u0.x; a0.y += v0.y + u0.y;
                a0.z += v0.z + u0.z; a0.w += v0.w + u0.w;
            }
            if (has1) {
                float4 v1 = __ldg(p0 + lane + 32);
                float4 u1 = __ldg(p1 + lane + 32);
                a1.x += v1.x + u1.x; a1.y += v1.y + u1.y;
                a1.z += v1.z + u1.z; a1.w += v1.w + u1.w;
            }
        }
        if (i < end) {
            int s = __ldg(indices + i);
            const float4* p = reinterpret_cast<const float4*>(feat + (size_t)s * dim);
            if (has0) {
                float4 v0 = __ldg(p + lane);
                a0.x += v0.x; a0.y += v0.y; a0.z += v0.z; a0.w += v0.w;
            }
            if (has1) {
                float4 v1 = __ldg(p + lane + 32);
                a1.x += v1.x; a1.y += v1.y; a1.z += v1.z; a1.w += v1.w;
            }
        }
        float4* q = reinterpret_cast<float4*>(aggout + (size_t)w * dim);
        if (has0) q[lane] = a0;
        if (has1) q[lane + 32] = a1;
    } else {
        float2 a0 = make_float2(0.f, 0.f);
        float2 a1 = make_float2(0.f, 0.f);
        int i = beg;
        for (; i + 1 < end; i += 2) {
            int s0 = __ldg(indices + i);
            int s1 = __ldg(indices + i + 1);
            const float2* p0 = reinterpret_cast<const float2*>(feat + (size_t)s0 * dim);
            const float2* p1 = reinterpret_cast<const float2*>(feat + (size_t)s1 * dim);
            if (has0) {
                float2 v0 = __ldg(p0 + lane);
                float2 u0 = __ldg(p1 + lane);
                a0.x += v0.x + u0.x; a0.y += v0.y + u0.y;
            }
            if (has1) {
                float2 v1 = __ldg(p0 + lane + 32);
                float2 u1 = __ldg(p1 + lane + 32);
                a1.x += v1.x + u1.x; a1.y += v1.y + u1.y;
            }
        }
        if (i < end) {
            int s = __ldg(indices + i);
            const float2* p = reinterpret_cast<const float2*>(feat + (size_t)s * dim);
            if (has0) {
                float2 v0 = __ldg(p + lane);
                a0.x += v0.x; a0.y += v0.y;
            }
            if (has1) {
                float2 v1 = __ldg(p + lane + 32);
                a1.x += v1.x; a1.y += v1.y;
            }
        }
        float2* q = reinterpret_cast<float2*>(aggout + (size_t)w * dim);
        if (has0) q[lane] = a0;
        if (has1) q[lane + 32] = a1;
    }
}

// ---------------------------------------------------------------------------
// TF32 tensor-core fused SAGE GEMM, reg-staged + LDMATRIX fragments (R10).
// ---------------------------------------------------------------------------
template <int VEC, bool HAS2, bool HASC, bool BIAS, bool RELU>
__global__ __launch_bounds__(256, 2)
void gemm_kernel(const float* __restrict__ A1, const uint32_t* __restrict__ W1,
                 const float* __restrict__ A2, const uint32_t* __restrict__ W2,
                 const float* __restrict__ Cin, const float* __restrict__ bias,
                 float* __restrict__ out, int N, int K, int O)
{
    constexpr int BM = 128, BN = 128, BK = 16, SW = 20;
    __shared__ uint32_t As[BM][SW];
    __shared__ uint32_t Ws[BN][SW];

    const int tid  = threadIdx.x;
    const int lane = tid & 31;
    const int warp = tid >> 5;
    const int wm   = warp & 1;
    const int wn   = warp >> 1;
    const int grp  = lane >> 2;
    const int qid  = lane & 3;
    const int bm0  = blockIdx.y * BM;
    const int bn0  = blockIdx.x * BN;

    const int nk = (K + BK - 1) / BK;
    const int T  = (HAS2 ? 2 : 1) * nk;

    const uint32_t asBase = (uint32_t)__cvta_generic_to_shared(&As[0][0]);
    const uint32_t wsBase = (uint32_t)__cvta_generic_to_shared(&Ws[0][0]);
    uint32_t aAddr[4];
#pragma unroll
    for (int i = 0; i < 4; i++) {
        int r = wm * 64 + i * 16 + (lane & 7) + ((lane >> 3) & 1) * 8;
        int c = ((lane >> 4) & 1) * 4;
        aAddr[i] = asBase + (uint32_t)(r * SW + c) * 4u;
    }
    uint32_t bAddr[2];
#pragma unroll
    for (int jp = 0; jp < 2; jp++) {
        int r = wn * 32 + jp * 16 + (lane & 7) + ((lane >> 4) & 1) * 8;
        int c = ((lane >> 3) & 1) * 4;
        bAddr[jp] = wsBase + (uint32_t)(r * SW + c) * 4u;
    }

    float    regA[8];
    uint32_t regW[8];

    auto prefetch = [&](int t) {
        const float*    A;
        const uint32_t* W;
        int k0;
        if (HAS2 && t >= nk) { A = A2; W = W2; k0 = (t - nk) * BK; }
        else                 { A = A1; W = W1; k0 = t * BK; }
        if (VEC == 4) {
#pragma unroll
            for (int i = 0; i < 2; i++) {
                int r = (tid >> 2) + i * 64;
                int k = (tid & 3) * 4;
                bool ok = (k0 + k) < K;
                int gr = min(bm0 + r, N - 1);
                int go = min(bn0 + r, O - 1);
                float4 va = ok ? *reinterpret_cast<const float4*>(A + (size_t)gr * K + k0 + k)
                               : make_float4(0.f, 0.f, 0.f, 0.f);
                uint4  vw = ok ? *reinterpret_cast<const uint4*>(W + (size_t)go * K + k0 + k)
                               : make_uint4(0u, 0u, 0u, 0u);
                regA[i*4+0] = va.x; regA[i*4+1] = va.y; regA[i*4+2] = va.z; regA[i*4+3] = va.w;
                regW[i*4+0] = vw.x; regW[i*4+1] = vw.y; regW[i*4+2] = vw.z; regW[i*4+3] = vw.w;
            }
        } else {
#pragma unroll
            for (int i = 0; i < 4; i++) {
                int r = (tid >> 3) + i * 32;
                int k = (tid & 7) * 2;
                bool ok = (k0 + k) < K;
                int gr = min(bm0 + r, N - 1);
                int go = min(bn0 + r, O - 1);
                float2 va = ok ? *reinterpret_cast<const float2*>(A + (size_t)gr * K + k0 + k)
                               : make_float2(0.f, 0.f);
                uint2  vw = ok ? *reinterpret_cast<const uint2*>(W + (size_t)go * K + k0 + k)
                               : make_uint2(0u, 0u);
                regA[i*2+0] = va.x; regA[i*2+1] = va.y;
                regW[i*2+0] = vw.x; regW[i*2+1] = vw.y;
            }
        }
    };

    auto commit = [&]() {
        if (VEC == 4) {
#pragma unroll
            for (int i = 0; i < 2; i++) {
                int r = (tid >> 2) + i * 64;
                int k = (tid & 3) * 4;
                uint4 ua = make_uint4(f32_to_tf32(regA[i*4+0]), f32_to_tf32(regA[i*4+1]),
                                      f32_to_tf32(regA[i*4+2]), f32_to_tf32(regA[i*4+3]));
                *reinterpret_cast<uint4*>(&As[r][k]) = ua;
                *reinterpret_cast<uint4*>(&Ws[r][k]) =
                    make_uint4(regW[i*4+0], regW[i*4+1], regW[i*4+2], regW[i*4+3]);
            }
        } else {
#pragma unroll
            for (int i = 0; i < 4; i++) {
                int r = (tid >> 3) + i * 32;
                int k = (tid & 7) * 2;
                *reinterpret_cast<uint2*>(&As[r][k]) =
                    make_uint2(f32_to_tf32(regA[i*2+0]), f32_to_tf32(regA[i*2+1]));
                *reinterpret_cast<uint2*>(&Ws[r][k]) = make_uint2(regW[i*2+0], regW[i*2+1]);
            }
        }
    };

    float acc[4][4][4];
#pragma unroll
    for (int i = 0; i < 4; i++)
#pragma unroll
        for (int j = 0; j < 4; j++)
#pragma unroll
            for (int f = 0; f < 4; f++) acc[i][j][f] = 0.f;

    prefetch(0);
    for (int t = 0; t < T; t++) {
        __syncthreads();
        commit();
        __syncthreads();
        if (t + 1 < T) prefetch(t + 1);

#pragma unroll
        for (int ks = 0; ks < BK; ks += 8) {
            uint32_t aF[4][4];
#pragma unroll
            for (int i = 0; i < 4; i++)
                ldsm_x4(aF[i][0], aF[i][1], aF[i][2], aF[i][3], aAddr[i] + (uint32_t)ks * 4u);
            uint32_t bF[4][2];
#pragma unroll
            for (int jp = 0; jp < 2; jp++)
                ldsm_x4(bF[jp*2][0], bF[jp*2][1], bF[jp*2+1][0], bF[jp*2+1][1],
                        bAddr[jp] + (uint32_t)ks * 4u);
#pragma unroll
            for (int i = 0; i < 4; i++)
#pragma unroll
                for (int j = 0; j < 4; j++) {
                    asm volatile(
                        "mma.sync.aligned.m16n8k8.row.col.f32.tf32.tf32.f32 "
                        "{%0,%1,%2,%3}, {%4,%5,%6,%7}, {%8,%9}, {%0,%1,%2,%3};"
                        : "+f"(acc[i][j][0]), "+f"(acc[i][j][1]),
                          "+f"(acc[i][j][2]), "+f"(acc[i][j][3])
                        : "r"(aF[i][0]), "r"(aF[i][1]),
                          "r"(aF[i][2]), "r"(aF[i][3]),
                          "r"(bF[j][0]), "r"(bF[j][1]));
                }
        }
    }

#pragma unroll
    for (int i = 0; i < 4; i++) {
        int row0 = bm0 + wm * 64 + i * 16 + grp;
#pragma unroll
        for (int j = 0; j < 4; j++) {
            int col0 = bn0 + wn * 32 + j * 8 + qid * 2;
            if (col0 >= O) continue;
            float2 bv;
            if (BIAS) bv = *reinterpret_cast<const float2*>(bias + col0);
#pragma unroll
            for (int h = 0; h < 2; h++) {
                int row = row0 + h * 8;
                if (row >= N) continue;
                float v0 = acc[i][j][h * 2 + 0];
                float v1 = acc[i][j][h * 2 + 1];
                if (BIAS) { v0 += bv.x; v1 += bv.y; }
                if (HASC) {
                    float2 cv = *reinterpret_cast<const float2*>(Cin + (size_t)row * O + col0);
                    v0 += cv.x; v1 += cv.y;
                }
                if (RELU) { v0 = fmaxf(v0, 0.f); v1 = fmaxf(v1, 0.f); }
                *reinterpret_cast<float2*>(out + (size_t)row * O + col0) = make_float2(v0, v1);
            }
        }
    }
}

// ---------------------------------------------------------------------------
// Global mean pool over sorted batch ids. One block per graph, 128 threads.
// ---------------------------------------------------------------------------
__global__ void pool_kernel(const float* __restrict__ h,
                            const int* __restrict__ batch,
                            int N, float* __restrict__ out, int col_off)
{
    int g = blockIdx.x;
    int lo = 0, hi = N;
    while (lo < hi) { int mid = (lo + hi) >> 1; if (batch[mid] < g) lo = mid + 1; else hi = mid; }
    int start = lo;
    hi = N;
    while (lo < hi) { int mid = (lo + hi) >> 1; if (batch[mid] < g + 1) lo = mid + 1; else hi = mid; }
    int end = lo;

    int c = threadIdx.x;
    float s = 0.f;
    for (int r = start; r < end; r++) s += h[(size_t)r * 128 + c];
    float cnt = (end > start) ? (float)(end - start) : 1.f;
    out[(size_t)g * 256 + col_off + c] = s / cnt;
}

// ---------------------------------------------------------------------------
// Host-side drivers (all stream-parameterized)
// ---------------------------------------------------------------------------
static inline dim3 gemm_grid(int N, int O) {
    return dim3((O + 127) / 128, (N + 127) / 128);
}

static void build_csr(const int* src, const int* dst, int N, int E,
                      int* indptr, int* cursor, int* indices, cudaStream_t st)
{
    cudaMemsetAsync(cursor, 0, (size_t)N * sizeof(int), st);
    hist_kernel<<<(E + 255) / 256, 256, 0, st>>>(dst, E, cursor);
    scan_kernel<<<1, 1024, 0, st>>>(cursor, N, indptr);
    copy_kernel<<<(N + 255) / 256, 256, 0, st>>>(indptr, cursor, N);
    scatter_kernel<<<(E + 255) / 256, 256, 0, st>>>(src, dst, E, cursor, indices);
}

static void launch_agg(const float* feat, const int* indptr, const int* indices,
                       float* agg, int N, int dim, cudaStream_t st)
{
    int blocks = (N + 7) / 8;
    if (dim % 4 == 0) csr_agg<4><<<blocks, 256, 0, st>>>(feat, indptr, indices, agg, N, dim);
    else              csr_agg<2><<<blocks, 256, 0, st>>>(feat, indptr, indices, agg, N, dim);
}

static void run_branch(const float* x, const int* indptr, const int* indices,
                       const int* batch, int N,
                       int d0, int d1, int d2,
                       const uint32_t* w1l, const float* b1, const uint32_t* w1r,
                       const uint32_t* w2l, const float* b2, const uint32_t* w2r,
                       const uint32_t* w3l, const float* b3, const uint32_t* w3r,
                       float* h1, float* h2, float* agg, float* t, float* h3,
                       float* out, int col_off, cudaStream_t st)
{
    // Layer 1
    launch_agg(x, indptr, indices, agg, N, d0, st);
    if (d0 % 4 == 0)
        gemm_kernel<4, true, false, true, true><<<gemm_grid(N, d1), 256, 0, st>>>(
            agg, w1l, x, w1r, nullptr, b1, h1, N, d0, d1);
    else
        gemm_kernel<2, true, false, true, true><<<gemm_grid(N, d1), 256, 0, st>>>(
            agg, w1l, x, w1r, nullptr, b1, h1, N, d0, d1);

    // Layer 2
    launch_agg(h1, indptr, indices, agg, N, d1, st);
    gemm_kernel<4, true, false, true, true><<<gemm_grid(N, d2), 256, 0, st>>>(
        agg, w2l, h1, w2r, nullptr, b2, h2, N, d1, d2);

    // Layer 3 (transform-first)
    gemm_kernel<4, false, false, false, false><<<gemm_grid(N, 128), 256, 0, st>>>(
        h2, w3l, nullptr, nullptr, nullptr, nullptr, t, N, d2, 128);
    launch_agg(t, indptr, indices, agg, N, 128, st);
    gemm_kernel<4, false, true, true, true><<<gemm_grid(N, 128), 256, 0, st>>>(
        h2, w3r, nullptr, nullptr, agg, b3, h3, N, d2, 128);

    pool_kernel<<<NG, 128, 0, st>>>(h3, batch, N, out, col_off);
}

extern "C" void kernel_launch(void* const* d_in, const int* in_sizes, int n_in,
                              void* d_out, int out_size)
{
    (void)n_in; (void)out_size; (void)in_sizes;

    // One-time side stream + fork/join events (created on the first,
    // uncaptured, correctness call; reused by the captured call).
    static cudaStream_t s2 = nullptr;
    static cudaEvent_t evFork = nullptr, evJoin = nullptr;
    if (s2 == nullptr) {
        cudaStreamCreateWithFlags(&s2, cudaStreamNonBlocking);
        cudaEventCreateWithFlags(&evFork, cudaEventDisableTiming);
        cudaEventCreateWithFlags(&evJoin, cudaEventDisableTiming);
    }
    cudaStream_t s0 = 0;

    const float* x        = (const float*)d_in[0];
    const int*   ei       = (const int*)  d_in[1];
    const int*   batch    = (const int*)  d_in[2];
    const float* xc       = (const float*)d_in[3];
    const int*   eic      = (const int*)  d_in[4];
    const int*   batchc   = (const int*)  d_in[5];

    const int wcnt[12] = {
        156*78, 156*78, 312*156, 312*156, 128*312, 128*312,
        184*92, 184*92, 368*184, 368*184, 128*368, 128*368
    };
    CvtArgs ca;
    ca.src[0]  = (const float*)d_in[6];   ca.src[1]  = (const float*)d_in[8];
    ca.src[2]  = (const float*)d_in[9];   ca.src[3]  = (const float*)d_in[11];
    ca.src[4]  = (const float*)d_in[12];  ca.src[5]  = (const float*)d_in[14];
    ca.src[6]  = (const float*)d_in[15];  ca.src[7]  = (const float*)d_in[17];
    ca.src[8]  = (const float*)d_in[18];  ca.src[9]  = (const float*)d_in[20];
    ca.src[10] = (const float*)d_in[21];  ca.src[11] = (const float*)d_in[23];
    ca.off[0] = 0;
    for (int i = 0; i < 12; i++) ca.off[i + 1] = ca.off[i] + wcnt[i];
    int wtotal = ca.off[12];

    const float* m1_bl = (const float*)d_in[7];
    const float* m2_bl = (const float*)d_in[10];
    const float* m3_bl = (const float*)d_in[13];
    const float* c1_bl = (const float*)d_in[16];
    const float* c2_bl = (const float*)d_in[19];
    const float* c3_bl = (const float*)d_in[22];

    float* out = (float*)d_out;

    float *mh1, *mh2, *magg, *mt, *mh3;
    float *ch1, *ch2, *cagg, *ct, *ch3;
    uint32_t* wt;
    int *ipm, *curm, *idxm, *ipc, *curc, *idxc;
    cudaGetSymbolAddress((void**)&mh1,  g_mh1);
    cudaGetSymbolAddress((void**)&mh2,  g_mh2);
    cudaGetSymbolAddress((void**)&magg, g_magg);
    cudaGetSymbolAddress((void**)&mt,   g_mt);
    cudaGetSymbolAddress((void**)&mh3,  g_mh3);
    cudaGetSymbolAddress((void**)&ch1,  g_ch1);
    cudaGetSymbolAddress((void**)&ch2,  g_ch2);
    cudaGetSymbolAddress((void**)&cagg, g_cagg);
    cudaGetSymbolAddress((void**)&ct,   g_ct);
    cudaGetSymbolAddress((void**)&ch3,  g_ch3);
    cudaGetSymbolAddress((void**)&wt,   g_wtf32);
    cudaGetSymbolAddress((void**)&ipm,  g_indptr_m);
    cudaGetSymbolAddress((void**)&curm, g_cursor_m);
    cudaGetSymbolAddress((void**)&idxm, g_indices_m);
    cudaGetSymbolAddress((void**)&ipc,  g_indptr_c);
    cudaGetSymbolAddress((void**)&curc, g_cursor_c);
    cudaGetSymbolAddress((void**)&idxc, g_indices_c);

    // Weights (needed by both branches) on s0, then fork.
    cvt_all_kernel<<<(wtotal + 255) / 256, 256, 0, s0>>>(ca, wt, wtotal);
    const uint32_t* wtf[12];
    for (int i = 0; i < 12; i++) wtf[i] = wt + ca.off[i];

    cudaEventRecord(evFork, s0);
    cudaStreamWaitEvent(s2, evFork, 0);

    // ---- side stream: clique branch (CSR build + 3 layers + pool) ----
    build_csr(eic, eic + E_CLQ, N_CLQ, E_CLQ, ipc, curc, idxc, s2);
    run_branch(xc, ipc, idxc, batchc, N_CLQ,
               92, 184, 368,
               wtf[6], c1_bl, wtf[7], wtf[8], c2_bl, wtf[9], wtf[10], c3_bl, wtf[11],
               ch1, ch2, cagg, ct, ch3, out, 128, s2);
    cudaEventRecord(evJoin, s2);

    // ---- main stream: molecule branch ----
    build_csr(ei, ei + E_MOL, N_MOL, E_MOL, ipm, curm, idxm, s0);
    run_branch(x, ipm, idxm, batch, N_MOL,
               78, 156, 312,
               wtf[0], m1_bl, wtf[1], wtf[2], m2_bl, wtf[3], wtf[4], m3_bl, wtf[5],
               mh1, mh2, magg, mt, mh3, out, 0, s0);

    cudaStreamWaitEvent(s0, evJoin, 0);
}